// round 1
// baseline (speedup 1.0000x reference)
#include <cuda_runtime.h>

#define HH 480
#define WW 640
#define HWP (HH*WW)          // 307200
#define BB 8
#define NEV 131072
#define SCALE 640.0f
#define EPSV 1e-9f

// Scratch: per-direction accumulator images, 4 floats per pixel:
// [pos_w, pos_w*ts, neg_w, neg_w*ts]
__device__ __align__(16) float g_acc0[BB * HWP * 4];   // tref = 1 (forward)
__device__ __align__(16) float g_acc1[BB * HWP * 4];   // tref = 0 (backward)

// Scalar accumulators (zero-initialized at load; final kernel re-zeros them)
__device__ float g_sum[2][BB];   // per-batch sum of per-pixel loss
__device__ float g_nz[2][BB];    // per-batch nonzero-pixel counts
__device__ float g_sm[4];        // smoothness sums: dx, dy, dr, ur

__device__ __forceinline__ float warp_red(float v) {
    #pragma unroll
    for (int o = 16; o > 0; o >>= 1) v += __shfl_down_sync(0xffffffffu, v, o);
    return v;
}

__device__ __forceinline__ void tap(float* base, int iy, int ix, float w, float wts) {
    if ((unsigned)iy < (unsigned)HH && (unsigned)ix < (unsigned)WW && w > 0.0f) {
        float* p = base + ((size_t)(iy * WW + ix) << 2);
        atomicAdd(p,     w);
        atomicAdd(p + 1, wts);
    }
}

__global__ void splat_kernel(const float* __restrict__ flow,
                             const float* __restrict__ ts,
                             const int*   __restrict__ ys,
                             const int*   __restrict__ xs,
                             const int*   __restrict__ pol) {
    int t = blockIdx.x * blockDim.x + threadIdx.x;
    if (t >= BB * NEV) return;
    int b = t >> 17;                      // NEV = 2^17
    int y = ys[t], x = xs[t];
    float t0 = ts[t];
    int p = pol[t];

    int flat = y * WW + x;
    const float* fb = flow + (size_t)b * 2 * HWP;
    float fxv = __ldg(fb + flat);
    float fyv = __ldg(fb + HWP + flat);

    int c = p ? 0 : 2;                    // pos events at lanes {0,1}, neg at {2,3}
    size_t bbase = (size_t)b * HWP * 4 + c;

    #pragma unroll
    for (int dir = 0; dir < 2; dir++) {
        float tref = (dir == 0) ? 1.0f : 0.0f;
        float dt   = tref - t0;
        float tsw  = (dir == 0) ? t0 : (1.0f - t0);

        float wy = (float)y + dt * fyv * SCALE;
        float wx = (float)x + dt * fxv * SCALE;
        float tyf = floorf(wy), lxf = floorf(wx);
        float ay = wy - tyf,    ax = wx - lxf;
        int ty = (int)tyf, lx = (int)lxf;

        float w00 = (1.0f - ay) * (1.0f - ax);
        float w01 = (1.0f - ay) * ax;
        float w10 = ay * (1.0f - ax);
        float w11 = ay * ax;

        float* base = ((dir == 0) ? g_acc0 : g_acc1) + bbase;
        tap(base, ty,     lx,     w00, w00 * tsw);
        tap(base, ty,     lx + 1, w01, w01 * tsw);
        tap(base, ty + 1, lx,     w10, w10 * tsw);
        tap(base, ty + 1, lx + 1, w11, w11 * tsw);
    }
}

// Per-pixel loss; zeroes scratch after reading (restores invariant for next replay)
__global__ void loss_kernel() {
    int p = blockIdx.x * blockDim.x + threadIdx.x;
    int b = blockIdx.y;
    float v0 = 0.f, v1 = 0.f, v2 = 0.f, v3 = 0.f;  // lfw, nzfw, lbw, nzbw
    if (p < HWP) {
        size_t off = ((size_t)b * HWP + p) << 2;
        float4* a0 = (float4*)(g_acc0 + off);
        float4 v = *a0;
        *a0 = make_float4(0.f, 0.f, 0.f, 0.f);
        float r0 = v.y / (v.x + EPSV);
        float r1 = v.w / (v.z + EPSV);
        v0 = r0 * r0 + r1 * r1;
        v1 = (v.x + v.z > 0.0f) ? 1.0f : 0.0f;

        float4* a1 = (float4*)(g_acc1 + off);
        float4 u = *a1;
        *a1 = make_float4(0.f, 0.f, 0.f, 0.f);
        float s0 = u.y / (u.x + EPSV);
        float s1 = u.w / (u.z + EPSV);
        v2 = s0 * s0 + s1 * s1;
        v3 = (u.x + u.z > 0.0f) ? 1.0f : 0.0f;
    }
    __shared__ float sm[4][8];
    int lane = threadIdx.x & 31, warp = threadIdx.x >> 5;
    v0 = warp_red(v0); v1 = warp_red(v1); v2 = warp_red(v2); v3 = warp_red(v3);
    if (lane == 0) { sm[0][warp] = v0; sm[1][warp] = v1; sm[2][warp] = v2; sm[3][warp] = v3; }
    __syncthreads();
    if (threadIdx.x == 0) {
        float a0 = 0.f, a1 = 0.f, a2 = 0.f, a3 = 0.f;
        #pragma unroll
        for (int i = 0; i < 8; i++) { a0 += sm[0][i]; a1 += sm[1][i]; a2 += sm[2][i]; a3 += sm[3][i]; }
        atomicAdd(&g_sum[0][b], a0);
        atomicAdd(&g_nz[0][b],  a1);
        atomicAdd(&g_sum[1][b], a2);
        atomicAdd(&g_nz[1][b],  a3);
    }
}

__device__ __forceinline__ float charb(float a, float b) {
    return sqrtf(a * a + b * b + 1e-6f);
}

__global__ void smooth_kernel(const float* __restrict__ flow) {
    int t = blockIdx.x * blockDim.x + threadIdx.x;
    float s0 = 0.f, s1 = 0.f, s2 = 0.f, s3 = 0.f;
    if (t < BB * HWP) {
        int b = t / HWP;
        int pix = t - b * HWP;
        int y = pix / WW;
        int x = pix - y * WW;
        const float* fx = flow + (size_t)b * 2 * HWP;
        const float* fy = fx + HWP;
        float fx00 = fx[pix], fy00 = fy[pix];
        bool xr = (x < WW - 1), yd = (y < HH - 1);
        float fx01 = 0.f, fy01 = 0.f, fx10 = 0.f, fy10 = 0.f, fx11 = 0.f, fy11 = 0.f;
        if (xr)       { fx01 = fx[pix + 1];      fy01 = fy[pix + 1]; }
        if (yd)       { fx10 = fx[pix + WW];     fy10 = fy[pix + WW]; }
        if (xr && yd) { fx11 = fx[pix + WW + 1]; fy11 = fy[pix + WW + 1]; }
        if (xr) s0 = charb(fx00 - fx01, fy00 - fy01);
        if (yd) s1 = charb(fx00 - fx10, fy00 - fy10);
        if (xr && yd) {
            s2 = charb(fx00 - fx11, fy00 - fy11);
            s3 = charb(fx10 - fx01, fy10 - fy01);
        }
    }
    __shared__ float sm[4][8];
    int lane = threadIdx.x & 31, warp = threadIdx.x >> 5;
    s0 = warp_red(s0); s1 = warp_red(s1); s2 = warp_red(s2); s3 = warp_red(s3);
    if (lane == 0) { sm[0][warp] = s0; sm[1][warp] = s1; sm[2][warp] = s2; sm[3][warp] = s3; }
    __syncthreads();
    if (threadIdx.x == 0) {
        float a0 = 0.f, a1 = 0.f, a2 = 0.f, a3 = 0.f;
        #pragma unroll
        for (int i = 0; i < 8; i++) { a0 += sm[0][i]; a1 += sm[1][i]; a2 += sm[2][i]; a3 += sm[3][i]; }
        atomicAdd(&g_sm[0], a0);
        atomicAdd(&g_sm[1], a1);
        atomicAdd(&g_sm[2], a2);
        atomicAdd(&g_sm[3], a3);
    }
}

__global__ void final_kernel(float* out, int n) {
    if (blockIdx.x == 0 && threadIdx.x == 0) {
        float loss = 0.0f;
        #pragma unroll
        for (int b = 0; b < BB; b++) {
            loss += g_sum[0][b] / g_nz[0][b];
            loss += g_sum[1][b] / g_nz[1][b];
        }
        float mdx = g_sm[0] / (float)(BB * HH * (WW - 1));
        float mdy = g_sm[1] / (float)(BB * (HH - 1) * WW);
        float mdr = g_sm[2] / (float)(BB * (HH - 1) * (WW - 1));
        float mur = g_sm[3] / (float)(BB * (HH - 1) * (WW - 1));
        loss += 0.001f * 0.25f * (mdx + mdy + mdr + mur);
        for (int i = 0; i < n; i++) out[i] = loss;
        // reset scalar accumulators for the next graph replay
        #pragma unroll
        for (int b = 0; b < BB; b++) {
            g_sum[0][b] = 0.f; g_sum[1][b] = 0.f;
            g_nz[0][b]  = 0.f; g_nz[1][b]  = 0.f;
        }
        #pragma unroll
        for (int i = 0; i < 4; i++) g_sm[i] = 0.f;
    }
}

extern "C" void kernel_launch(void* const* d_in, const int* in_sizes, int n_in,
                              void* d_out, int out_size) {
    const float* flow = (const float*)d_in[0];
    const float* ts   = (const float*)d_in[1];
    const int*   ys   = (const int*)d_in[2];
    const int*   xs   = (const int*)d_in[3];
    const int*   pol  = (const int*)d_in[4];

    int totE = BB * NEV;
    splat_kernel<<<(totE + 255) / 256, 256>>>(flow, ts, ys, xs, pol);
    smooth_kernel<<<(BB * HWP + 255) / 256, 256>>>(flow);
    dim3 g((HWP + 255) / 256, BB);
    loss_kernel<<<g, 256>>>();
    final_kernel<<<1, 32>>>((float*)d_out, out_size);
}

// round 2
// speedup vs baseline: 1.1083x; 1.1083x over previous
#include <cuda_runtime.h>

#define HH 480
#define WW 640
#define HWP (HH*WW)          // 307200
#define BB 8
#define NEV 131072
#define SCALE 640.0f
#define EPSV 1e-9f

// Scratch: per-direction accumulator images, 4 floats per pixel:
// [pos_w, pos_w*ts, neg_w, neg_w*ts]
__device__ __align__(16) float g_acc0[BB * HWP * 4];   // tref = 1 (forward)
__device__ __align__(16) float g_acc1[BB * HWP * 4];   // tref = 0 (backward)

// Scalar accumulators (zero-initialized at load; final kernel re-zeros them)
__device__ float g_sum[2][BB];
__device__ float g_nz[2][BB];
__device__ float g_sm[4];

__device__ __forceinline__ float warp_red(float v) {
    #pragma unroll
    for (int o = 16; o > 0; o >>= 1) v += __shfl_down_sync(0xffffffffu, v, o);
    return v;
}

// Vectorized global reduction: one 8B transaction adds {a,b} to p[0],p[1].
__device__ __forceinline__ void red2(float* p, float a, float b) {
    asm volatile("red.global.add.v2.f32 [%0], {%1, %2};"
                 :: "l"(p), "f"(a), "f"(b) : "memory");
}

__device__ __forceinline__ void tap(float* base, int iy, int ix, float w, float wts) {
    if ((unsigned)iy < (unsigned)HH && (unsigned)ix < (unsigned)WW) {
        red2(base + ((size_t)(iy * WW + ix) << 2), w, wts);
    }
}

__global__ void __launch_bounds__(256) splat_kernel(
        const float* __restrict__ flow,
        const float* __restrict__ ts,
        const int*   __restrict__ ys,
        const int*   __restrict__ xs,
        const int*   __restrict__ pol) {
    int t = blockIdx.x * blockDim.x + threadIdx.x;
    if (t >= BB * NEV) return;
    int b = t >> 17;                      // NEV = 2^17
    int y = ys[t], x = xs[t];
    float t0 = ts[t];
    int p = pol[t];

    int flat = y * WW + x;
    const float* fb = flow + (size_t)b * 2 * HWP;
    float fxv = __ldg(fb + flat) * SCALE;
    float fyv = __ldg(fb + HWP + flat) * SCALE;

    int c = p ? 0 : 2;                    // pos events at lanes {0,1}, neg at {2,3}
    size_t bbase = ((size_t)b * HWP << 2) + c;

    #pragma unroll
    for (int dir = 0; dir < 2; dir++) {
        float dt  = (dir == 0) ? (1.0f - t0) : (-t0);
        float tsw = (dir == 0) ? t0 : (1.0f - t0);

        float wy = (float)y + dt * fyv;
        float wx = (float)x + dt * fxv;
        float tyf = floorf(wy), lxf = floorf(wx);
        float ay = wy - tyf,    ax = wx - lxf;
        int ty = (int)tyf, lx = (int)lxf;

        float w00 = (1.0f - ay) * (1.0f - ax);
        float w01 = (1.0f - ay) * ax;
        float w10 = ay * (1.0f - ax);
        float w11 = ay * ax;

        float* base = ((dir == 0) ? g_acc0 : g_acc1) + bbase;
        tap(base, ty,     lx,     w00, w00 * tsw);
        tap(base, ty,     lx + 1, w01, w01 * tsw);
        tap(base, ty + 1, lx,     w10, w10 * tsw);
        tap(base, ty + 1, lx + 1, w11, w11 * tsw);
    }
}

// Per-pixel loss; zeroes scratch after reading (restores invariant for next replay)
__global__ void __launch_bounds__(256) loss_kernel() {
    int p = blockIdx.x * blockDim.x + threadIdx.x;
    int b = blockIdx.y;
    float v0 = 0.f, v1 = 0.f, v2 = 0.f, v3 = 0.f;
    if (p < HWP) {
        size_t off = ((size_t)b * HWP + p) << 2;
        float4* a0 = (float4*)(g_acc0 + off);
        float4 v = *a0;
        *a0 = make_float4(0.f, 0.f, 0.f, 0.f);
        float r0 = v.y / (v.x + EPSV);
        float r1 = v.w / (v.z + EPSV);
        v0 = r0 * r0 + r1 * r1;
        v1 = (v.x + v.z > 0.0f) ? 1.0f : 0.0f;

        float4* a1 = (float4*)(g_acc1 + off);
        float4 u = *a1;
        *a1 = make_float4(0.f, 0.f, 0.f, 0.f);
        float s0 = u.y / (u.x + EPSV);
        float s1 = u.w / (u.z + EPSV);
        v2 = s0 * s0 + s1 * s1;
        v3 = (u.x + u.z > 0.0f) ? 1.0f : 0.0f;
    }
    __shared__ float sm[4][8];
    int lane = threadIdx.x & 31, warp = threadIdx.x >> 5;
    v0 = warp_red(v0); v1 = warp_red(v1); v2 = warp_red(v2); v3 = warp_red(v3);
    if (lane == 0) { sm[0][warp] = v0; sm[1][warp] = v1; sm[2][warp] = v2; sm[3][warp] = v3; }
    __syncthreads();
    if (threadIdx.x == 0) {
        float a0 = 0.f, a1 = 0.f, a2 = 0.f, a3 = 0.f;
        #pragma unroll
        for (int i = 0; i < 8; i++) { a0 += sm[0][i]; a1 += sm[1][i]; a2 += sm[2][i]; a3 += sm[3][i]; }
        atomicAdd(&g_sum[0][b], a0);
        atomicAdd(&g_nz[0][b],  a1);
        atomicAdd(&g_sum[1][b], a2);
        atomicAdd(&g_nz[1][b],  a3);
    }
}

__device__ __forceinline__ float charb(float a, float b) {
    return sqrtf(a * a + b * b + 1e-6f);
}

__global__ void __launch_bounds__(256) smooth_kernel(const float* __restrict__ flow) {
    int t = blockIdx.x * blockDim.x + threadIdx.x;
    float s0 = 0.f, s1 = 0.f, s2 = 0.f, s3 = 0.f;
    if (t < BB * HWP) {
        int b = t / HWP;
        int pix = t - b * HWP;
        int y = pix / WW;
        int x = pix - y * WW;
        const float* fx = flow + (size_t)b * 2 * HWP;
        const float* fy = fx + HWP;
        float fx00 = fx[pix], fy00 = fy[pix];
        bool xr = (x < WW - 1), yd = (y < HH - 1);
        float fx01 = 0.f, fy01 = 0.f, fx10 = 0.f, fy10 = 0.f, fx11 = 0.f, fy11 = 0.f;
        if (xr)       { fx01 = fx[pix + 1];      fy01 = fy[pix + 1]; }
        if (yd)       { fx10 = fx[pix + WW];     fy10 = fy[pix + WW]; }
        if (xr && yd) { fx11 = fx[pix + WW + 1]; fy11 = fy[pix + WW + 1]; }
        if (xr) s0 = charb(fx00 - fx01, fy00 - fy01);
        if (yd) s1 = charb(fx00 - fx10, fy00 - fy10);
        if (xr && yd) {
            s2 = charb(fx00 - fx11, fy00 - fy11);
            s3 = charb(fx10 - fx01, fy10 - fy01);
        }
    }
    __shared__ float sm[4][8];
    int lane = threadIdx.x & 31, warp = threadIdx.x >> 5;
    s0 = warp_red(s0); s1 = warp_red(s1); s2 = warp_red(s2); s3 = warp_red(s3);
    if (lane == 0) { sm[0][warp] = s0; sm[1][warp] = s1; sm[2][warp] = s2; sm[3][warp] = s3; }
    __syncthreads();
    if (threadIdx.x == 0) {
        float a0 = 0.f, a1 = 0.f, a2 = 0.f, a3 = 0.f;
        #pragma unroll
        for (int i = 0; i < 8; i++) { a0 += sm[0][i]; a1 += sm[1][i]; a2 += sm[2][i]; a3 += sm[3][i]; }
        atomicAdd(&g_sm[0], a0);
        atomicAdd(&g_sm[1], a1);
        atomicAdd(&g_sm[2], a2);
        atomicAdd(&g_sm[3], a3);
    }
}

__global__ void final_kernel(float* out, int n) {
    if (blockIdx.x == 0 && threadIdx.x == 0) {
        float loss = 0.0f;
        #pragma unroll
        for (int b = 0; b < BB; b++) {
            loss += g_sum[0][b] / g_nz[0][b];
            loss += g_sum[1][b] / g_nz[1][b];
        }
        float mdx = g_sm[0] / (float)(BB * HH * (WW - 1));
        float mdy = g_sm[1] / (float)(BB * (HH - 1) * WW);
        float mdr = g_sm[2] / (float)(BB * (HH - 1) * (WW - 1));
        float mur = g_sm[3] / (float)(BB * (HH - 1) * (WW - 1));
        loss += 0.001f * 0.25f * (mdx + mdy + mdr + mur);
        for (int i = 0; i < n; i++) out[i] = loss;
        #pragma unroll
        for (int b = 0; b < BB; b++) {
            g_sum[0][b] = 0.f; g_sum[1][b] = 0.f;
            g_nz[0][b]  = 0.f; g_nz[1][b]  = 0.f;
        }
        #pragma unroll
        for (int i = 0; i < 4; i++) g_sm[i] = 0.f;
    }
}

extern "C" void kernel_launch(void* const* d_in, const int* in_sizes, int n_in,
                              void* d_out, int out_size) {
    const float* flow = (const float*)d_in[0];
    const float* ts   = (const float*)d_in[1];
    const int*   ys   = (const int*)d_in[2];
    const int*   xs   = (const int*)d_in[3];
    const int*   pol  = (const int*)d_in[4];

    int totE = BB * NEV;
    splat_kernel<<<(totE + 255) / 256, 256>>>(flow, ts, ys, xs, pol);
    smooth_kernel<<<(BB * HWP + 255) / 256, 256>>>(flow);
    dim3 g((HWP + 255) / 256, BB);
    loss_kernel<<<g, 256>>>();
    final_kernel<<<1, 32>>>((float*)d_out, out_size);
}

// round 3
// speedup vs baseline: 1.5008x; 1.3541x over previous
#include <cuda_runtime.h>

#define HH 480
#define WW 640
#define HWP (HH*WW)          // 307200
#define BB 8
#define NEV 131072
#define SCALE 640.0f
#define EPSV 1e-9f

// One accumulator image per phase direction, 4 floats per pixel:
// [pos_w, pos_w*ts, neg_w, neg_w*ts].  78.6 MB each; phases run sequentially
// so only one is hot at a time (fits L2 with the event data).
__device__ __align__(16) float g_acc0[BB * HWP * 4];   // forward  (tref = 1)
__device__ __align__(16) float g_acc1[BB * HWP * 4];   // backward (tref = 0)

// Scalar accumulators (zero-initialized at load; final kernel re-zeros them)
__device__ float g_sum[2][BB];
__device__ float g_nz[2][BB];
__device__ float g_sm[4];

__device__ __forceinline__ float warp_red(float v) {
    #pragma unroll
    for (int o = 16; o > 0; o >>= 1) v += __shfl_down_sync(0xffffffffu, v, o);
    return v;
}

// Vectorized global reduction: one 8B transaction adds {a,b} to p[0],p[1].
__device__ __forceinline__ void red2(float* p, float a, float b) {
    asm volatile("red.global.add.v2.f32 [%0], {%1, %2};"
                 :: "l"(p), "f"(a), "f"(b) : "memory");
}

__device__ __forceinline__ void tap(float* base, int iy, int ix, float w, float wts) {
    if ((unsigned)iy < (unsigned)HH && (unsigned)ix < (unsigned)WW) {
        red2(base + ((size_t)(iy * WW + ix) << 2), w, wts);
    }
}

// DIR = 0: forward (tref=1, ts_w = ts); DIR = 1: backward (tref=0, ts_w = 1-ts)
template <int DIR>
__global__ void __launch_bounds__(256) splat_kernel(
        const float* __restrict__ flow,
        const float* __restrict__ ts,
        const int*   __restrict__ ys,
        const int*   __restrict__ xs,
        const int*   __restrict__ pol) {
    int t = blockIdx.x * blockDim.x + threadIdx.x;
    if (t >= BB * NEV) return;
    int b = t >> 17;                      // NEV = 2^17
    int y = ys[t], x = xs[t];
    float t0 = ts[t];
    int p = pol[t];

    int flat = y * WW + x;
    const float* fb = flow + (size_t)b * 2 * HWP;
    float fxv = __ldg(fb + flat) * SCALE;
    float fyv = __ldg(fb + HWP + flat) * SCALE;

    int c = p ? 0 : 2;                    // pos events at lanes {0,1}, neg at {2,3}
    size_t bbase = ((size_t)b * HWP << 2) + c;

    float dt  = (DIR == 0) ? (1.0f - t0) : (-t0);
    float tsw = (DIR == 0) ? t0 : (1.0f - t0);

    float wy = (float)y + dt * fyv;
    float wx = (float)x + dt * fxv;
    float tyf = floorf(wy), lxf = floorf(wx);
    float ay = wy - tyf,    ax = wx - lxf;
    int ty = (int)tyf, lx = (int)lxf;

    float w00 = (1.0f - ay) * (1.0f - ax);
    float w01 = (1.0f - ay) * ax;
    float w10 = ay * (1.0f - ax);
    float w11 = ay * ax;

    float* base = ((DIR == 0) ? g_acc0 : g_acc1) + bbase;
    tap(base, ty,     lx,     w00, w00 * tsw);
    tap(base, ty,     lx + 1, w01, w01 * tsw);
    tap(base, ty + 1, lx,     w10, w10 * tsw);
    tap(base, ty + 1, lx + 1, w11, w11 * tsw);
}

// Per-pixel loss for one direction; zeroes scratch after reading.
template <int DIR>
__global__ void __launch_bounds__(256) loss_kernel() {
    int p = blockIdx.x * blockDim.x + threadIdx.x;
    int b = blockIdx.y;
    float v0 = 0.f, v1 = 0.f;
    if (p < HWP) {
        size_t off = ((size_t)b * HWP + p) << 2;
        float4* a = (float4*)(((DIR == 0) ? g_acc0 : g_acc1) + off);
        float4 v = *a;
        *a = make_float4(0.f, 0.f, 0.f, 0.f);
        float r0 = v.y / (v.x + EPSV);
        float r1 = v.w / (v.z + EPSV);
        v0 = r0 * r0 + r1 * r1;
        v1 = (v.x + v.z > 0.0f) ? 1.0f : 0.0f;
    }
    __shared__ float sm[2][8];
    int lane = threadIdx.x & 31, warp = threadIdx.x >> 5;
    v0 = warp_red(v0); v1 = warp_red(v1);
    if (lane == 0) { sm[0][warp] = v0; sm[1][warp] = v1; }
    __syncthreads();
    if (threadIdx.x == 0) {
        float a0 = 0.f, a1 = 0.f;
        #pragma unroll
        for (int i = 0; i < 8; i++) { a0 += sm[0][i]; a1 += sm[1][i]; }
        atomicAdd(&g_sum[DIR][b], a0);
        atomicAdd(&g_nz[DIR][b],  a1);
    }
}

__device__ __forceinline__ float charb(float a, float b) {
    return sqrtf(a * a + b * b + 1e-6f);
}

__global__ void __launch_bounds__(256) smooth_kernel(const float* __restrict__ flow) {
    int t = blockIdx.x * blockDim.x + threadIdx.x;
    float s0 = 0.f, s1 = 0.f, s2 = 0.f, s3 = 0.f;
    if (t < BB * HWP) {
        int b = t / HWP;
        int pix = t - b * HWP;
        int y = pix / WW;
        int x = pix - y * WW;
        const float* fx = flow + (size_t)b * 2 * HWP;
        const float* fy = fx + HWP;
        float fx00 = fx[pix], fy00 = fy[pix];
        bool xr = (x < WW - 1), yd = (y < HH - 1);
        float fx01 = 0.f, fy01 = 0.f, fx10 = 0.f, fy10 = 0.f, fx11 = 0.f, fy11 = 0.f;
        if (xr)       { fx01 = fx[pix + 1];      fy01 = fy[pix + 1]; }
        if (yd)       { fx10 = fx[pix + WW];     fy10 = fy[pix + WW]; }
        if (xr && yd) { fx11 = fx[pix + WW + 1]; fy11 = fy[pix + WW + 1]; }
        if (xr) s0 = charb(fx00 - fx01, fy00 - fy01);
        if (yd) s1 = charb(fx00 - fx10, fy00 - fy10);
        if (xr && yd) {
            s2 = charb(fx00 - fx11, fy00 - fy11);
            s3 = charb(fx10 - fx01, fy10 - fy01);
        }
    }
    __shared__ float sm[4][8];
    int lane = threadIdx.x & 31, warp = threadIdx.x >> 5;
    s0 = warp_red(s0); s1 = warp_red(s1); s2 = warp_red(s2); s3 = warp_red(s3);
    if (lane == 0) { sm[0][warp] = s0; sm[1][warp] = s1; sm[2][warp] = s2; sm[3][warp] = s3; }
    __syncthreads();
    if (threadIdx.x == 0) {
        float a0 = 0.f, a1 = 0.f, a2 = 0.f, a3 = 0.f;
        #pragma unroll
        for (int i = 0; i < 8; i++) { a0 += sm[0][i]; a1 += sm[1][i]; a2 += sm[2][i]; a3 += sm[3][i]; }
        atomicAdd(&g_sm[0], a0);
        atomicAdd(&g_sm[1], a1);
        atomicAdd(&g_sm[2], a2);
        atomicAdd(&g_sm[3], a3);
    }
}

__global__ void final_kernel(float* out, int n) {
    if (blockIdx.x == 0 && threadIdx.x == 0) {
        float loss = 0.0f;
        #pragma unroll
        for (int b = 0; b < BB; b++) {
            loss += g_sum[0][b] / g_nz[0][b];
            loss += g_sum[1][b] / g_nz[1][b];
        }
        float mdx = g_sm[0] / (float)(BB * HH * (WW - 1));
        float mdy = g_sm[1] / (float)(BB * (HH - 1) * WW);
        float mdr = g_sm[2] / (float)(BB * (HH - 1) * (WW - 1));
        float mur = g_sm[3] / (float)(BB * (HH - 1) * (WW - 1));
        loss += 0.001f * 0.25f * (mdx + mdy + mdr + mur);
        for (int i = 0; i < n; i++) out[i] = loss;
        #pragma unroll
        for (int b = 0; b < BB; b++) {
            g_sum[0][b] = 0.f; g_sum[1][b] = 0.f;
            g_nz[0][b]  = 0.f; g_nz[1][b]  = 0.f;
        }
        #pragma unroll
        for (int i = 0; i < 4; i++) g_sm[i] = 0.f;
    }
}

extern "C" void kernel_launch(void* const* d_in, const int* in_sizes, int n_in,
                              void* d_out, int out_size) {
    const float* flow = (const float*)d_in[0];
    const float* ts   = (const float*)d_in[1];
    const int*   ys   = (const int*)d_in[2];
    const int*   xs   = (const int*)d_in[3];
    const int*   pol  = (const int*)d_in[4];

    int totE = BB * NEV;
    int eBlocks = (totE + 255) / 256;
    dim3 g((HWP + 255) / 256, BB);

    // Phase 1: forward. Working set = g_acc0 (78.6 MB) + events — fits L2.
    splat_kernel<0><<<eBlocks, 256>>>(flow, ts, ys, xs, pol);
    loss_kernel<0><<<g, 256>>>();
    // Phase 2: backward.
    splat_kernel<1><<<eBlocks, 256>>>(flow, ts, ys, xs, pol);
    loss_kernel<1><<<g, 256>>>();

    smooth_kernel<<<(BB * HWP + 255) / 256, 256>>>(flow);
    final_kernel<<<1, 32>>>((float*)d_out, out_size);
}

// round 4
// speedup vs baseline: 1.6738x; 1.1153x over previous
#include <cuda_runtime.h>

#define HH 480
#define WW 640
#define HWP (HH*WW)          // 307200
#define BB 8
#define NEV 131072
#define PHB 2                // batches per phase
#define NPH (BB/PHB)         // 4 phases
#define SCALE 640.0f
#define EPSV 1e-9f

// Phase-local accumulator: [localb][dir][pixel][4 channels]
// channels: [pos_w, pos_w*ts, neg_w, neg_w*ts].  39.3 MB — L2-resident.
// Zero at static init; each loss pass restores zeros for the next phase/replay.
__device__ __align__(16) float g_acc[PHB * 2 * HWP * 4];

// Scalar accumulators (zero-initialized at load; final kernel re-zeros them)
__device__ float g_sum[2][BB];
__device__ float g_nz[2][BB];
__device__ float g_sm[4];

__device__ __forceinline__ float warp_red(float v) {
    #pragma unroll
    for (int o = 16; o > 0; o >>= 1) v += __shfl_down_sync(0xffffffffu, v, o);
    return v;
}

// Vectorized global reduction: one 8B transaction adds {a,b} to p[0],p[1].
__device__ __forceinline__ void red2(float* p, float a, float b) {
    asm volatile("red.global.add.v2.f32 [%0], {%1, %2};"
                 :: "l"(p), "f"(a), "f"(b) : "memory");
}

__device__ __forceinline__ void tap(float* base, int iy, int ix, float w, float wts) {
    if ((unsigned)iy < (unsigned)HH && (unsigned)ix < (unsigned)WW) {
        red2(base + ((size_t)(iy * WW + ix) << 2), w, wts);
    }
}

// One phase: events of batches [b0, b0+PHB), both directions.
__global__ void __launch_bounds__(256) splat_kernel(
        const float* __restrict__ flow,
        const float* __restrict__ ts,
        const int*   __restrict__ ys,
        const int*   __restrict__ xs,
        const int*   __restrict__ pol,
        int b0) {
    int t = blockIdx.x * blockDim.x + threadIdx.x;
    if (t >= PHB * NEV) return;
    int lb = t >> 17;                     // NEV = 2^17
    int b  = b0 + lb;
    int e  = (b << 17) + (t & (NEV - 1));

    int y = ys[e], x = xs[e];
    float t0 = ts[e];
    int p = pol[e];

    int flat = y * WW + x;
    const float* fb = flow + (size_t)b * 2 * HWP;
    float fxv = __ldg(fb + flat) * SCALE;
    float fyv = __ldg(fb + HWP + flat) * SCALE;

    int c = p ? 0 : 2;                    // pos events at lanes {0,1}, neg at {2,3}

    #pragma unroll
    for (int dir = 0; dir < 2; dir++) {
        float dt  = (dir == 0) ? (1.0f - t0) : (-t0);
        float tsw = (dir == 0) ? t0 : (1.0f - t0);

        float wy = (float)y + dt * fyv;
        float wx = (float)x + dt * fxv;
        float tyf = floorf(wy), lxf = floorf(wx);
        float ay = wy - tyf,    ax = wx - lxf;
        int ty = (int)tyf, lx = (int)lxf;

        float w00 = (1.0f - ay) * (1.0f - ax);
        float w01 = (1.0f - ay) * ax;
        float w10 = ay * (1.0f - ax);
        float w11 = ay * ax;

        float* base = g_acc + ((size_t)((lb * 2 + dir) * HWP) << 2) + c;
        tap(base, ty,     lx,     w00, w00 * tsw);
        tap(base, ty,     lx + 1, w01, w01 * tsw);
        tap(base, ty + 1, lx,     w10, w10 * tsw);
        tap(base, ty + 1, lx + 1, w11, w11 * tsw);
    }
}

// Per-pixel loss for one phase (PHB batches x 2 dirs); zeroes scratch after read.
__global__ void __launch_bounds__(256) loss_kernel(int b0) {
    int p   = blockIdx.x * blockDim.x + threadIdx.x;
    int img = blockIdx.y;                 // 0..PHB*2-1  = lb*2 + dir
    int lb  = img >> 1;
    int dir = img & 1;
    int b   = b0 + lb;
    float v0 = 0.f, v1 = 0.f;
    if (p < HWP) {
        float4* a = (float4*)(g_acc + ((size_t)(img * HWP + p) << 2));
        float4 v = *a;
        *a = make_float4(0.f, 0.f, 0.f, 0.f);
        float r0 = v.y / (v.x + EPSV);
        float r1 = v.w / (v.z + EPSV);
        v0 = r0 * r0 + r1 * r1;
        v1 = (v.x + v.z > 0.0f) ? 1.0f : 0.0f;
    }
    __shared__ float sm[2][8];
    int lane = threadIdx.x & 31, warp = threadIdx.x >> 5;
    v0 = warp_red(v0); v1 = warp_red(v1);
    if (lane == 0) { sm[0][warp] = v0; sm[1][warp] = v1; }
    __syncthreads();
    if (threadIdx.x == 0) {
        float a0 = 0.f, a1 = 0.f;
        #pragma unroll
        for (int i = 0; i < 8; i++) { a0 += sm[0][i]; a1 += sm[1][i]; }
        atomicAdd(&g_sum[dir][b], a0);
        atomicAdd(&g_nz[dir][b],  a1);
    }
}

__device__ __forceinline__ float charb(float a, float b) {
    return sqrtf(a * a + b * b + 1e-6f);
}

__global__ void __launch_bounds__(256) smooth_kernel(const float* __restrict__ flow) {
    int t = blockIdx.x * blockDim.x + threadIdx.x;
    float s0 = 0.f, s1 = 0.f, s2 = 0.f, s3 = 0.f;
    if (t < BB * HWP) {
        int b = t / HWP;
        int pix = t - b * HWP;
        int y = pix / WW;
        int x = pix - y * WW;
        const float* fx = flow + (size_t)b * 2 * HWP;
        const float* fy = fx + HWP;
        float fx00 = fx[pix], fy00 = fy[pix];
        bool xr = (x < WW - 1), yd = (y < HH - 1);
        float fx01 = 0.f, fy01 = 0.f, fx10 = 0.f, fy10 = 0.f, fx11 = 0.f, fy11 = 0.f;
        if (xr)       { fx01 = fx[pix + 1];      fy01 = fy[pix + 1]; }
        if (yd)       { fx10 = fx[pix + WW];     fy10 = fy[pix + WW]; }
        if (xr && yd) { fx11 = fx[pix + WW + 1]; fy11 = fy[pix + WW + 1]; }
        if (xr) s0 = charb(fx00 - fx01, fy00 - fy01);
        if (yd) s1 = charb(fx00 - fx10, fy00 - fy10);
        if (xr && yd) {
            s2 = charb(fx00 - fx11, fy00 - fy11);
            s3 = charb(fx10 - fx01, fy10 - fy01);
        }
    }
    __shared__ float sm[4][8];
    int lane = threadIdx.x & 31, warp = threadIdx.x >> 5;
    s0 = warp_red(s0); s1 = warp_red(s1); s2 = warp_red(s2); s3 = warp_red(s3);
    if (lane == 0) { sm[0][warp] = s0; sm[1][warp] = s1; sm[2][warp] = s2; sm[3][warp] = s3; }
    __syncthreads();
    if (threadIdx.x == 0) {
        float a0 = 0.f, a1 = 0.f, a2 = 0.f, a3 = 0.f;
        #pragma unroll
        for (int i = 0; i < 8; i++) { a0 += sm[0][i]; a1 += sm[1][i]; a2 += sm[2][i]; a3 += sm[3][i]; }
        atomicAdd(&g_sm[0], a0);
        atomicAdd(&g_sm[1], a1);
        atomicAdd(&g_sm[2], a2);
        atomicAdd(&g_sm[3], a3);
    }
}

__global__ void final_kernel(float* out, int n) {
    if (blockIdx.x == 0 && threadIdx.x == 0) {
        float loss = 0.0f;
        #pragma unroll
        for (int b = 0; b < BB; b++) {
            loss += g_sum[0][b] / g_nz[0][b];
            loss += g_sum[1][b] / g_nz[1][b];
        }
        float mdx = g_sm[0] / (float)(BB * HH * (WW - 1));
        float mdy = g_sm[1] / (float)(BB * (HH - 1) * WW);
        float mdr = g_sm[2] / (float)(BB * (HH - 1) * (WW - 1));
        float mur = g_sm[3] / (float)(BB * (HH - 1) * (WW - 1));
        loss += 0.001f * 0.25f * (mdx + mdy + mdr + mur);
        for (int i = 0; i < n; i++) out[i] = loss;
        #pragma unroll
        for (int b = 0; b < BB; b++) {
            g_sum[0][b] = 0.f; g_sum[1][b] = 0.f;
            g_nz[0][b]  = 0.f; g_nz[1][b]  = 0.f;
        }
        #pragma unroll
        for (int i = 0; i < 4; i++) g_sm[i] = 0.f;
    }
}

extern "C" void kernel_launch(void* const* d_in, const int* in_sizes, int n_in,
                              void* d_out, int out_size) {
    const float* flow = (const float*)d_in[0];
    const float* ts   = (const float*)d_in[1];
    const int*   ys   = (const int*)d_in[2];
    const int*   xs   = (const int*)d_in[3];
    const int*   pol  = (const int*)d_in[4];

    int eBlocks = (PHB * NEV + 255) / 256;        // 1024
    dim3 lg((HWP + 255) / 256, PHB * 2);

    for (int ph = 0; ph < NPH; ph++) {
        int b0 = ph * PHB;
        splat_kernel<<<eBlocks, 256>>>(flow, ts, ys, xs, pol, b0);
        loss_kernel<<<lg, 256>>>(b0);
    }
    smooth_kernel<<<(BB * HWP + 255) / 256, 256>>>(flow);
    final_kernel<<<1, 32>>>((float*)d_out, out_size);
}

// round 5
// speedup vs baseline: 1.9285x; 1.1522x over previous
#include <cuda_runtime.h>
#include <cuda_fp16.h>

#define HH 480
#define WW 640
#define HWP (HH*WW)          // 307200
#define BB 8
#define NEV 131072
#define SCALE 640.0f
#define EPSV 1e-9f

// fp16 accumulator: [b][dir][pixel][4 halves: pos_w, pos_ts, neg_w, neg_ts]
// 8 bytes per pixel-image, total 39.3 MB — fully L2-resident.
// Zero at static init; loss pass restores zeros for the next replay.
__device__ __align__(16) __half2 g_acc[BB * 2 * HWP * 2];

// Scalar accumulators (zero-initialized at load; final kernel re-zeros them)
__device__ float g_sum[2][BB];
__device__ float g_nz[2][BB];
__device__ float g_sm[4];

__device__ __forceinline__ float warp_red(float v) {
    #pragma unroll
    for (int o = 16; o > 0; o >>= 1) v += __shfl_down_sync(0xffffffffu, v, o);
    return v;
}

__device__ __forceinline__ unsigned pack2(float a, float b) {
    __half2 h = __floats2half2_rn(a, b);
    return *reinterpret_cast<unsigned*>(&h);
}

// One 8B vector reduction adds 4 halves at p.
__device__ __forceinline__ void red4h(__half2* p, unsigned lo, unsigned hi) {
    asm volatile("red.global.add.noftz.v2.f16x2 [%0], {%1, %2};"
                 :: "l"(p), "r"(lo), "r"(hi) : "memory");
}

__device__ __forceinline__ void tap(__half2* base, int iy, int ix,
                                    float w, float tsw, bool pos) {
    if ((unsigned)iy < (unsigned)HH && (unsigned)ix < (unsigned)WW) {
        unsigned wp = pack2(w, w * tsw);
        unsigned lo = pos ? wp : 0u;
        unsigned hi = pos ? 0u : wp;
        red4h(base + ((size_t)(iy * WW + ix) << 1), lo, hi);
    }
}

__global__ void __launch_bounds__(256) splat_kernel(
        const float* __restrict__ flow,
        const float* __restrict__ ts,
        const int*   __restrict__ ys,
        const int*   __restrict__ xs,
        const int*   __restrict__ pol) {
    int t = blockIdx.x * blockDim.x + threadIdx.x;
    if (t >= BB * NEV) return;
    int b = t >> 17;                      // NEV = 2^17
    int y = ys[t], x = xs[t];
    float t0 = ts[t];
    bool pos = (pol[t] != 0);

    int flat = y * WW + x;
    const float* fb = flow + (size_t)b * 2 * HWP;
    float fxv = __ldg(fb + flat) * SCALE;
    float fyv = __ldg(fb + HWP + flat) * SCALE;

    #pragma unroll
    for (int dir = 0; dir < 2; dir++) {
        float dt  = (dir == 0) ? (1.0f - t0) : (-t0);
        float tsw = (dir == 0) ? t0 : (1.0f - t0);

        float wy = (float)y + dt * fyv;
        float wx = (float)x + dt * fxv;
        float tyf = floorf(wy), lxf = floorf(wx);
        float ay = wy - tyf,    ax = wx - lxf;
        int ty = (int)tyf, lx = (int)lxf;

        float w00 = (1.0f - ay) * (1.0f - ax);
        float w01 = (1.0f - ay) * ax;
        float w10 = ay * (1.0f - ax);
        float w11 = ay * ax;

        __half2* base = g_acc + ((size_t)((b * 2 + dir) * HWP) << 1);
        tap(base, ty,     lx,     w00, tsw, pos);
        tap(base, ty,     lx + 1, w01, tsw, pos);
        tap(base, ty + 1, lx,     w10, tsw, pos);
        tap(base, ty + 1, lx + 1, w11, tsw, pos);
    }
}

// Per-pixel loss over all images; zeroes scratch after reading.
__global__ void __launch_bounds__(256) loss_kernel() {
    int p   = blockIdx.x * blockDim.x + threadIdx.x;
    int img = blockIdx.y;                 // b*2 + dir
    int b   = img >> 1;
    int dir = img & 1;
    float v0 = 0.f, v1 = 0.f;
    if (p < HWP) {
        uint2* a = (uint2*)(g_acc + ((size_t)(img * HWP + p) << 1));
        uint2 v = *a;
        *a = make_uint2(0u, 0u);
        __half2 hp = *reinterpret_cast<__half2*>(&v.x);
        __half2 hn = *reinterpret_cast<__half2*>(&v.y);
        float pw  = __low2float(hp),  pts = __high2float(hp);
        float nw  = __low2float(hn),  nts = __high2float(hn);
        float r0 = pts / (pw + EPSV);
        float r1 = nts / (nw + EPSV);
        v0 = r0 * r0 + r1 * r1;
        v1 = (pw + nw > 0.0f) ? 1.0f : 0.0f;
    }
    __shared__ float sm[2][8];
    int lane = threadIdx.x & 31, warp = threadIdx.x >> 5;
    v0 = warp_red(v0); v1 = warp_red(v1);
    if (lane == 0) { sm[0][warp] = v0; sm[1][warp] = v1; }
    __syncthreads();
    if (threadIdx.x == 0) {
        float a0 = 0.f, a1 = 0.f;
        #pragma unroll
        for (int i = 0; i < 8; i++) { a0 += sm[0][i]; a1 += sm[1][i]; }
        atomicAdd(&g_sum[dir][b], a0);
        atomicAdd(&g_nz[dir][b],  a1);
    }
}

__device__ __forceinline__ float charb(float a, float b) {
    return sqrtf(a * a + b * b + 1e-6f);
}

__global__ void __launch_bounds__(256) smooth_kernel(const float* __restrict__ flow) {
    int t = blockIdx.x * blockDim.x + threadIdx.x;
    float s0 = 0.f, s1 = 0.f, s2 = 0.f, s3 = 0.f;
    if (t < BB * HWP) {
        int b = t / HWP;
        int pix = t - b * HWP;
        int y = pix / WW;
        int x = pix - y * WW;
        const float* fx = flow + (size_t)b * 2 * HWP;
        const float* fy = fx + HWP;
        float fx00 = fx[pix], fy00 = fy[pix];
        bool xr = (x < WW - 1), yd = (y < HH - 1);
        float fx01 = 0.f, fy01 = 0.f, fx10 = 0.f, fy10 = 0.f, fx11 = 0.f, fy11 = 0.f;
        if (xr)       { fx01 = fx[pix + 1];      fy01 = fy[pix + 1]; }
        if (yd)       { fx10 = fx[pix + WW];     fy10 = fy[pix + WW]; }
        if (xr && yd) { fx11 = fx[pix + WW + 1]; fy11 = fy[pix + WW + 1]; }
        if (xr) s0 = charb(fx00 - fx01, fy00 - fy01);
        if (yd) s1 = charb(fx00 - fx10, fy00 - fy10);
        if (xr && yd) {
            s2 = charb(fx00 - fx11, fy00 - fy11);
            s3 = charb(fx10 - fx01, fy10 - fy01);
        }
    }
    __shared__ float sm[4][8];
    int lane = threadIdx.x & 31, warp = threadIdx.x >> 5;
    s0 = warp_red(s0); s1 = warp_red(s1); s2 = warp_red(s2); s3 = warp_red(s3);
    if (lane == 0) { sm[0][warp] = s0; sm[1][warp] = s1; sm[2][warp] = s2; sm[3][warp] = s3; }
    __syncthreads();
    if (threadIdx.x == 0) {
        float a0 = 0.f, a1 = 0.f, a2 = 0.f, a3 = 0.f;
        #pragma unroll
        for (int i = 0; i < 8; i++) { a0 += sm[0][i]; a1 += sm[1][i]; a2 += sm[2][i]; a3 += sm[3][i]; }
        atomicAdd(&g_sm[0], a0);
        atomicAdd(&g_sm[1], a1);
        atomicAdd(&g_sm[2], a2);
        atomicAdd(&g_sm[3], a3);
    }
}

__global__ void final_kernel(float* out, int n) {
    if (blockIdx.x == 0 && threadIdx.x == 0) {
        float loss = 0.0f;
        #pragma unroll
        for (int b = 0; b < BB; b++) {
            loss += g_sum[0][b] / g_nz[0][b];
            loss += g_sum[1][b] / g_nz[1][b];
        }
        float mdx = g_sm[0] / (float)(BB * HH * (WW - 1));
        float mdy = g_sm[1] / (float)(BB * (HH - 1) * WW);
        float mdr = g_sm[2] / (float)(BB * (HH - 1) * (WW - 1));
        float mur = g_sm[3] / (float)(BB * (HH - 1) * (WW - 1));
        loss += 0.001f * 0.25f * (mdx + mdy + mdr + mur);
        for (int i = 0; i < n; i++) out[i] = loss;
        #pragma unroll
        for (int b = 0; b < BB; b++) {
            g_sum[0][b] = 0.f; g_sum[1][b] = 0.f;
            g_nz[0][b]  = 0.f; g_nz[1][b]  = 0.f;
        }
        #pragma unroll
        for (int i = 0; i < 4; i++) g_sm[i] = 0.f;
    }
}

extern "C" void kernel_launch(void* const* d_in, const int* in_sizes, int n_in,
                              void* d_out, int out_size) {
    const float* flow = (const float*)d_in[0];
    const float* ts   = (const float*)d_in[1];
    const int*   ys   = (const int*)d_in[2];
    const int*   xs   = (const int*)d_in[3];
    const int*   pol  = (const int*)d_in[4];

    int totE = BB * NEV;
    splat_kernel<<<(totE + 255) / 256, 256>>>(flow, ts, ys, xs, pol);
    smooth_kernel<<<(BB * HWP + 255) / 256, 256>>>(flow);
    dim3 lg((HWP + 255) / 256, BB * 2);
    loss_kernel<<<lg, 256>>>();
    final_kernel<<<1, 32>>>((float*)d_out, out_size);
}

// round 6
// speedup vs baseline: 2.1162x; 1.0973x over previous
#include <cuda_runtime.h>
#include <cuda_fp16.h>

#define HH 480
#define WW 640
#define HWP (HH*WW)          // 307200
#define BB 8
#define NEV 131072
#define SCALE 640.0f
#define EPSV 1e-9f

// fp16 accumulator: [b][dir][pixel][4 halves: pos_w, pos_ts, neg_w, neg_ts]
// 8 bytes per pixel, total 39.3 MB — L2-resident.
// Zero at static init; loss pass restores zeros for the next replay.
__device__ __align__(16) __half2 g_acc[BB * 2 * HWP * 2];

// Scalar accumulators (zero-initialized at load; final kernel re-zeros them)
__device__ float g_sum[2][BB];
__device__ float g_nz[2][BB];
__device__ float g_sm[4];

__device__ __forceinline__ float warp_red(float v) {
    #pragma unroll
    for (int o = 16; o > 0; o >>= 1) v += __shfl_down_sync(0xffffffffu, v, o);
    return v;
}

__device__ __forceinline__ unsigned pack2(float a, float b) {
    __half2 h = __floats2half2_rn(a, b);
    return *reinterpret_cast<unsigned*>(&h);
}

// 8B reduction: adds 4 halves (one pixel).
__device__ __forceinline__ void red8(__half2* p, unsigned lo, unsigned hi) {
    asm volatile("red.global.add.noftz.v2.f16x2 [%0], {%1, %2};"
                 :: "l"(p), "r"(lo), "r"(hi) : "memory");
}
// 16B reduction: adds 8 halves (two adjacent pixels) in ONE instruction.
__device__ __forceinline__ void red16(__half2* p, unsigned a, unsigned b,
                                      unsigned c, unsigned d) {
    asm volatile("red.global.add.noftz.v4.f16x2 [%0], {%1, %2, %3, %4};"
                 :: "l"(p), "r"(a), "r"(b), "r"(c), "r"(d) : "memory");
}

// One bilinear row: taps (iy,lx) and (iy,lx+1). Merge into one 16B red when
// lx is even and both in-bounds; otherwise fall back to per-tap 8B reds.
__device__ __forceinline__ void row_taps(__half2* img, int iy, int lx,
                                         float wl, float wr, float tsw, bool pos) {
    if ((unsigned)iy >= (unsigned)HH) return;
    bool vl = (unsigned)lx < (unsigned)WW;
    bool vr = (unsigned)(lx + 1) < (unsigned)WW;
    unsigned pl = pack2(wl, wl * tsw);
    unsigned pr = pack2(wr, wr * tsw);
    unsigned l0 = pos ? pl : 0u, l1 = pos ? 0u : pl;
    unsigned r0 = pos ? pr : 0u, r1 = pos ? 0u : pr;
    size_t row = (size_t)iy * WW;
    if (((lx & 1) == 0) && vl && vr) {
        red16(img + ((row + lx) << 1), l0, l1, r0, r1);
    } else {
        if (vl) red8(img + ((row + lx)     << 1), l0, l1);
        if (vr) red8(img + ((row + lx + 1) << 1), r0, r1);
    }
}

__global__ void __launch_bounds__(256) splat_kernel(
        const float* __restrict__ flow,
        const float* __restrict__ ts,
        const int*   __restrict__ ys,
        const int*   __restrict__ xs,
        const int*   __restrict__ pol) {
    int t = blockIdx.x * blockDim.x + threadIdx.x;
    if (t >= BB * NEV) return;
    int b = t >> 17;                      // NEV = 2^17
    int y = ys[t], x = xs[t];
    float t0 = ts[t];
    bool pos = (pol[t] != 0);

    int flat = y * WW + x;
    const float* fb = flow + (size_t)b * 2 * HWP;
    float fxv = __ldg(fb + flat) * SCALE;
    float fyv = __ldg(fb + HWP + flat) * SCALE;

    #pragma unroll
    for (int dir = 0; dir < 2; dir++) {
        float dt  = (dir == 0) ? (1.0f - t0) : (-t0);
        float tsw = (dir == 0) ? t0 : (1.0f - t0);

        float wy = (float)y + dt * fyv;
        float wx = (float)x + dt * fxv;
        float tyf = floorf(wy), lxf = floorf(wx);
        float ay = wy - tyf,    ax = wx - lxf;
        int ty = (int)tyf, lx = (int)lxf;

        float w00 = (1.0f - ay) * (1.0f - ax);
        float w01 = (1.0f - ay) * ax;
        float w10 = ay * (1.0f - ax);
        float w11 = ay * ax;

        __half2* img = g_acc + ((size_t)((b * 2 + dir) * HWP) << 1);
        row_taps(img, ty,     lx, w00, w01, tsw, pos);
        row_taps(img, ty + 1, lx, w10, w11, tsw, pos);
    }
}

// Per-pixel loss; each thread handles TWO pixels (one 16B slot); zeroes after read.
__global__ void __launch_bounds__(256) loss_kernel() {
    int s   = blockIdx.x * blockDim.x + threadIdx.x;   // slot = pixel pair
    int img = blockIdx.y;                 // b*2 + dir
    int b   = img >> 1;
    int dir = img & 1;
    float v0 = 0.f, v1 = 0.f;
    if (s < HWP / 2) {
        uint4* a = (uint4*)(g_acc + ((size_t)img * HWP + (size_t)s * 2) * 2);
        uint4 v = *a;
        *a = make_uint4(0u, 0u, 0u, 0u);
        #pragma unroll
        for (int k = 0; k < 2; k++) {
            unsigned up = k ? v.z : v.x;
            unsigned un = k ? v.w : v.y;
            __half2 hp = *reinterpret_cast<__half2*>(&up);
            __half2 hn = *reinterpret_cast<__half2*>(&un);
            float pw  = __low2float(hp),  pts = __high2float(hp);
            float nw  = __low2float(hn),  nts = __high2float(hn);
            float r0 = pts / (pw + EPSV);
            float r1 = nts / (nw + EPSV);
            v0 += r0 * r0 + r1 * r1;
            v1 += (pw + nw > 0.0f) ? 1.0f : 0.0f;
        }
    }
    __shared__ float sm[2][8];
    int lane = threadIdx.x & 31, warp = threadIdx.x >> 5;
    v0 = warp_red(v0); v1 = warp_red(v1);
    if (lane == 0) { sm[0][warp] = v0; sm[1][warp] = v1; }
    __syncthreads();
    if (threadIdx.x == 0) {
        float a0 = 0.f, a1 = 0.f;
        #pragma unroll
        for (int i = 0; i < 8; i++) { a0 += sm[0][i]; a1 += sm[1][i]; }
        atomicAdd(&g_sum[dir][b], a0);
        atomicAdd(&g_nz[dir][b],  a1);
    }
}

__device__ __forceinline__ float charb(float a, float b) {
    return sqrtf(a * a + b * b + 1e-6f);
}

__global__ void __launch_bounds__(256) smooth_kernel(const float* __restrict__ flow) {
    int t = blockIdx.x * blockDim.x + threadIdx.x;
    float s0 = 0.f, s1 = 0.f, s2 = 0.f, s3 = 0.f;
    if (t < BB * HWP) {
        int b = t / HWP;
        int pix = t - b * HWP;
        int y = pix / WW;
        int x = pix - y * WW;
        const float* fx = flow + (size_t)b * 2 * HWP;
        const float* fy = fx + HWP;
        float fx00 = fx[pix], fy00 = fy[pix];
        bool xr = (x < WW - 1), yd = (y < HH - 1);
        float fx01 = 0.f, fy01 = 0.f, fx10 = 0.f, fy10 = 0.f, fx11 = 0.f, fy11 = 0.f;
        if (xr)       { fx01 = fx[pix + 1];      fy01 = fy[pix + 1]; }
        if (yd)       { fx10 = fx[pix + WW];     fy10 = fy[pix + WW]; }
        if (xr && yd) { fx11 = fx[pix + WW + 1]; fy11 = fy[pix + WW + 1]; }
        if (xr) s0 = charb(fx00 - fx01, fy00 - fy01);
        if (yd) s1 = charb(fx00 - fx10, fy00 - fy10);
        if (xr && yd) {
            s2 = charb(fx00 - fx11, fy00 - fy11);
            s3 = charb(fx10 - fx01, fy10 - fy01);
        }
    }
    __shared__ float sm[4][8];
    int lane = threadIdx.x & 31, warp = threadIdx.x >> 5;
    s0 = warp_red(s0); s1 = warp_red(s1); s2 = warp_red(s2); s3 = warp_red(s3);
    if (lane == 0) { sm[0][warp] = s0; sm[1][warp] = s1; sm[2][warp] = s2; sm[3][warp] = s3; }
    __syncthreads();
    if (threadIdx.x == 0) {
        float a0 = 0.f, a1 = 0.f, a2 = 0.f, a3 = 0.f;
        #pragma unroll
        for (int i = 0; i < 8; i++) { a0 += sm[0][i]; a1 += sm[1][i]; a2 += sm[2][i]; a3 += sm[3][i]; }
        atomicAdd(&g_sm[0], a0);
        atomicAdd(&g_sm[1], a1);
        atomicAdd(&g_sm[2], a2);
        atomicAdd(&g_sm[3], a3);
    }
}

__global__ void final_kernel(float* out, int n) {
    if (blockIdx.x == 0 && threadIdx.x == 0) {
        float loss = 0.0f;
        #pragma unroll
        for (int b = 0; b < BB; b++) {
            loss += g_sum[0][b] / g_nz[0][b];
            loss += g_sum[1][b] / g_nz[1][b];
        }
        float mdx = g_sm[0] / (float)(BB * HH * (WW - 1));
        float mdy = g_sm[1] / (float)(BB * (HH - 1) * WW);
        float mdr = g_sm[2] / (float)(BB * (HH - 1) * (WW - 1));
        float mur = g_sm[3] / (float)(BB * (HH - 1) * (WW - 1));
        loss += 0.001f * 0.25f * (mdx + mdy + mdr + mur);
        for (int i = 0; i < n; i++) out[i] = loss;
        #pragma unroll
        for (int b = 0; b < BB; b++) {
            g_sum[0][b] = 0.f; g_sum[1][b] = 0.f;
            g_nz[0][b]  = 0.f; g_nz[1][b]  = 0.f;
        }
        #pragma unroll
        for (int i = 0; i < 4; i++) g_sm[i] = 0.f;
    }
}

extern "C" void kernel_launch(void* const* d_in, const int* in_sizes, int n_in,
                              void* d_out, int out_size) {
    const float* flow = (const float*)d_in[0];
    const float* ts   = (const float*)d_in[1];
    const int*   ys   = (const int*)d_in[2];
    const int*   xs   = (const int*)d_in[3];
    const int*   pol  = (const int*)d_in[4];

    int totE = BB * NEV;
    // smooth launched FIRST so ncu's skip-count lands on the splat next capture.
    smooth_kernel<<<(BB * HWP + 255) / 256, 256>>>(flow);
    splat_kernel<<<(totE + 255) / 256, 256>>>(flow, ts, ys, xs, pol);
    dim3 lg((HWP / 2 + 255) / 256, BB * 2);
    loss_kernel<<<lg, 256>>>();
    final_kernel<<<1, 32>>>((float*)d_out, out_size);
}

// round 7
// speedup vs baseline: 2.4942x; 1.1786x over previous
#include <cuda_runtime.h>
#include <cuda_fp16.h>

#define HH 480
#define WW 640
#define HWP (HH*WW)          // 307200
#define BB 8
#define NEV 131072
#define SCALE 640.0f
#define EPSV 1e-9f

#define SPLAT_BLOCKS ((BB*NEV)/256)            // 4096
#define SMOOTH_BLOCKS ((BB*HWP + 255)/256)     // 9600
#define FUSED_BLOCKS (SPLAT_BLOCKS + SMOOTH_BLOCKS)
#define LOSS_GX ((HWP/2 + 255)/256)            // 300
#define LOSS_BLOCKS (LOSS_GX * BB * 2)

// fp16 accumulator: [b][dir][pixel][4 halves: pos_w, pos_ts, neg_w, neg_ts]
// 8 B/pixel, 39.3 MB total — L2-resident. Zero at init; loss restores zeros.
__device__ __align__(16) __half2 g_acc[BB * 2 * HWP * 2];

__device__ float g_sum[2][BB];
__device__ float g_nz[2][BB];
__device__ float g_sm[4];
__device__ unsigned g_done = 0;

__device__ __forceinline__ float warp_red(float v) {
    #pragma unroll
    for (int o = 16; o > 0; o >>= 1) v += __shfl_down_sync(0xffffffffu, v, o);
    return v;
}

__device__ __forceinline__ unsigned pack2(float a, float b) {
    __half2 h = __floats2half2_rn(a, b);
    return *reinterpret_cast<unsigned*>(&h);
}

__device__ __forceinline__ void red8(__half2* p, unsigned lo, unsigned hi) {
    asm volatile("red.global.add.noftz.v2.f16x2 [%0], {%1, %2};"
                 :: "l"(p), "r"(lo), "r"(hi) : "memory");
}
__device__ __forceinline__ void red16(__half2* p, unsigned a, unsigned b,
                                      unsigned c, unsigned d) {
    asm volatile("red.global.add.noftz.v4.f16x2 [%0], {%1, %2, %3, %4};"
                 :: "l"(p), "r"(a), "r"(b), "r"(c), "r"(d) : "memory");
}

__device__ __forceinline__ void row_taps(__half2* img, int iy, int lx,
                                         float wl, float wr, float tsw, bool pos) {
    if ((unsigned)iy >= (unsigned)HH) return;
    bool vl = (unsigned)lx < (unsigned)WW;
    bool vr = (unsigned)(lx + 1) < (unsigned)WW;
    unsigned pl = pack2(wl, wl * tsw);
    unsigned pr = pack2(wr, wr * tsw);
    unsigned l0 = pos ? pl : 0u, l1 = pos ? 0u : pl;
    unsigned r0 = pos ? pr : 0u, r1 = pos ? 0u : pr;
    size_t row = (size_t)iy * WW;
    if (((lx & 1) == 0) && vl && vr) {
        red16(img + ((row + lx) << 1), l0, l1, r0, r1);
    } else {
        if (vl) red8(img + ((row + lx)     << 1), l0, l1);
        if (vr) red8(img + ((row + lx + 1) << 1), r0, r1);
    }
}

__device__ __forceinline__ void splat_work(
        int blk,
        const float* __restrict__ flow, const float* __restrict__ ts,
        const int* __restrict__ ys, const int* __restrict__ xs,
        const int* __restrict__ pol) {
    int t = blk * 256 + threadIdx.x;
    int b = t >> 17;                      // NEV = 2^17
    int y = ys[t], x = xs[t];
    float t0 = ts[t];
    bool pos = (pol[t] != 0);

    int flat = y * WW + x;
    const float* fb = flow + (size_t)b * 2 * HWP;
    float fxv = __ldg(fb + flat) * SCALE;
    float fyv = __ldg(fb + HWP + flat) * SCALE;

    #pragma unroll
    for (int dir = 0; dir < 2; dir++) {
        float dt  = (dir == 0) ? (1.0f - t0) : (-t0);
        float tsw = (dir == 0) ? t0 : (1.0f - t0);

        float wy = (float)y + dt * fyv;
        float wx = (float)x + dt * fxv;
        float tyf = floorf(wy), lxf = floorf(wx);
        float ay = wy - tyf,    ax = wx - lxf;
        int ty = (int)tyf, lx = (int)lxf;

        float w00 = (1.0f - ay) * (1.0f - ax);
        float w01 = (1.0f - ay) * ax;
        float w10 = ay * (1.0f - ax);
        float w11 = ay * ax;

        __half2* img = g_acc + ((size_t)((b * 2 + dir) * HWP) << 1);
        row_taps(img, ty,     lx, w00, w01, tsw, pos);
        row_taps(img, ty + 1, lx, w10, w11, tsw, pos);
    }
}

__device__ __forceinline__ float charb(float a, float b) {
    return sqrtf(a * a + b * b + 1e-6f);
}

__device__ __forceinline__ void smooth_work(int blk, const float* __restrict__ flow) {
    int t = blk * 256 + threadIdx.x;
    float s0 = 0.f, s1 = 0.f, s2 = 0.f, s3 = 0.f;
    if (t < BB * HWP) {
        int b = t / HWP;
        int pix = t - b * HWP;
        int y = pix / WW;
        int x = pix - y * WW;
        const float* fx = flow + (size_t)b * 2 * HWP;
        const float* fy = fx + HWP;
        float fx00 = fx[pix], fy00 = fy[pix];
        bool xr = (x < WW - 1), yd = (y < HH - 1);
        float fx01 = 0.f, fy01 = 0.f, fx10 = 0.f, fy10 = 0.f, fx11 = 0.f, fy11 = 0.f;
        if (xr)       { fx01 = fx[pix + 1];      fy01 = fy[pix + 1]; }
        if (yd)       { fx10 = fx[pix + WW];     fy10 = fy[pix + WW]; }
        if (xr && yd) { fx11 = fx[pix + WW + 1]; fy11 = fy[pix + WW + 1]; }
        if (xr) s0 = charb(fx00 - fx01, fy00 - fy01);
        if (yd) s1 = charb(fx00 - fx10, fy00 - fy10);
        if (xr && yd) {
            s2 = charb(fx00 - fx11, fy00 - fy11);
            s3 = charb(fx10 - fx01, fy10 - fy01);
        }
    }
    __shared__ float sm[4][8];
    int lane = threadIdx.x & 31, warp = threadIdx.x >> 5;
    s0 = warp_red(s0); s1 = warp_red(s1); s2 = warp_red(s2); s3 = warp_red(s3);
    if (lane == 0) { sm[0][warp] = s0; sm[1][warp] = s1; sm[2][warp] = s2; sm[3][warp] = s3; }
    __syncthreads();
    if (threadIdx.x == 0) {
        float a0 = 0.f, a1 = 0.f, a2 = 0.f, a3 = 0.f;
        #pragma unroll
        for (int i = 0; i < 8; i++) { a0 += sm[0][i]; a1 += sm[1][i]; a2 += sm[2][i]; a3 += sm[3][i]; }
        atomicAdd(&g_sm[0], a0);
        atomicAdd(&g_sm[1], a1);
        atomicAdd(&g_sm[2], a2);
        atomicAdd(&g_sm[3], a3);
    }
}

// Heterogeneous kernel: splat + smooth blocks Bresenham-interleaved so every
// wave co-schedules atomic-bound and MUFU-bound work on each SM.
__global__ void __launch_bounds__(256) fused_kernel(
        const float* __restrict__ flow, const float* __restrict__ ts,
        const int* __restrict__ ys, const int* __restrict__ xs,
        const int* __restrict__ pol) {
    int bid = blockIdx.x;
    long long sb  = ((long long)bid * SPLAT_BLOCKS) / FUSED_BLOCKS;
    long long sb1 = ((long long)(bid + 1) * SPLAT_BLOCKS) / FUSED_BLOCKS;
    if (sb1 > sb) {
        splat_work((int)sb, flow, ts, ys, xs, pol);
    } else {
        smooth_work(bid - (int)sb, flow);
    }
}

// Per-pixel loss (2 px/thread); zeroes scratch; last block computes the final scalar.
__global__ void __launch_bounds__(256) loss_kernel(float* out, int n) {
    int s   = blockIdx.x * blockDim.x + threadIdx.x;   // pixel pair
    int img = blockIdx.y;                 // b*2 + dir
    int b   = img >> 1;
    int dir = img & 1;
    float v0 = 0.f, v1 = 0.f;
    if (s < HWP / 2) {
        uint4* a = (uint4*)(g_acc + ((size_t)img * HWP + (size_t)s * 2) * 2);
        uint4 v = *a;
        *a = make_uint4(0u, 0u, 0u, 0u);
        #pragma unroll
        for (int k = 0; k < 2; k++) {
            unsigned up = k ? v.z : v.x;
            unsigned un = k ? v.w : v.y;
            __half2 hp = *reinterpret_cast<__half2*>(&up);
            __half2 hn = *reinterpret_cast<__half2*>(&un);
            float pw  = __low2float(hp),  pts = __high2float(hp);
            float nw  = __low2float(hn),  nts = __high2float(hn);
            float r0 = pts / (pw + EPSV);
            float r1 = nts / (nw + EPSV);
            v0 += r0 * r0 + r1 * r1;
            v1 += (pw + nw > 0.0f) ? 1.0f : 0.0f;
        }
    }
    __shared__ float sm[2][8];
    int lane = threadIdx.x & 31, warp = threadIdx.x >> 5;
    v0 = warp_red(v0); v1 = warp_red(v1);
    if (lane == 0) { sm[0][warp] = v0; sm[1][warp] = v1; }
    __syncthreads();
    if (threadIdx.x == 0) {
        float a0 = 0.f, a1 = 0.f;
        #pragma unroll
        for (int i = 0; i < 8; i++) { a0 += sm[0][i]; a1 += sm[1][i]; }
        atomicAdd(&g_sum[dir][b], a0);
        atomicAdd(&g_nz[dir][b],  a1);
        __threadfence();
        unsigned done = atomicAdd(&g_done, 1u);
        if (done == LOSS_BLOCKS - 1) {
            // last block: all g_sum/g_nz visible; g_sm done since fused_kernel finished.
            float loss = 0.0f;
            #pragma unroll
            for (int bb = 0; bb < BB; bb++) {
                loss += g_sum[0][bb] / g_nz[0][bb];
                loss += g_sum[1][bb] / g_nz[1][bb];
            }
            float mdx = g_sm[0] / (float)(BB * HH * (WW - 1));
            float mdy = g_sm[1] / (float)(BB * (HH - 1) * WW);
            float mdr = g_sm[2] / (float)(BB * (HH - 1) * (WW - 1));
            float mur = g_sm[3] / (float)(BB * (HH - 1) * (WW - 1));
            loss += 0.001f * 0.25f * (mdx + mdy + mdr + mur);
            for (int i = 0; i < n; i++) out[i] = loss;
            // reset accumulators for the next graph replay
            #pragma unroll
            for (int bb = 0; bb < BB; bb++) {
                g_sum[0][bb] = 0.f; g_sum[1][bb] = 0.f;
                g_nz[0][bb]  = 0.f; g_nz[1][bb]  = 0.f;
            }
            #pragma unroll
            for (int i = 0; i < 4; i++) g_sm[i] = 0.f;
            g_done = 0;
        }
    }
}

extern "C" void kernel_launch(void* const* d_in, const int* in_sizes, int n_in,
                              void* d_out, int out_size) {
    const float* flow = (const float*)d_in[0];
    const float* ts   = (const float*)d_in[1];
    const int*   ys   = (const int*)d_in[2];
    const int*   xs   = (const int*)d_in[3];
    const int*   pol  = (const int*)d_in[4];

    fused_kernel<<<FUSED_BLOCKS, 256>>>(flow, ts, ys, xs, pol);
    dim3 lg(LOSS_GX, BB * 2);
    loss_kernel<<<lg, 256>>>((float*)d_out, out_size);
}